// round 2
// baseline (speedup 1.0000x reference)
#include <cuda_runtime.h>
#include <cuda_bf16.h>

#define THR_LO 0.6f
#define THR_HI 0.8f

// Global accumulators: n_sim, n_disim, sim_sum, disim_sum
__device__ double g_acc[4];
// Edge index width flag: 1 = int64 indices, 0 = int32 indices
__device__ int g_is64;

__global__ void lp_init_kernel(const int* __restrict__ edges_w32, int n_words) {
    if (threadIdx.x < 4) g_acc[threadIdx.x] = 0.0;
    if (threadIdx.x == 0) {
        // Probe: if edges are int64 (values < 2^31), every odd 32-bit word
        // (high half) is 0. For int32 edges, odd words are j-indices, ~all nonzero.
        int probe = n_words < 256 ? n_words : 256;
        int all_odd_zero = 1;
        for (int w = 1; w < probe; w += 2) {
            if (edges_w32[w] != 0) { all_odd_zero = 0; break; }
        }
        g_is64 = all_odd_zero;
    }
}

__global__ void __launch_bounds__(256)
lp_edge_kernel(const void* __restrict__ edges,
               const float* __restrict__ probas,
               const float* __restrict__ feats,
               int n_edges, int n_nodes) {
    float n_sim = 0.f, n_dis = 0.f, s_sim = 0.f, s_dis = 0.f;

    const int is64 = g_is64;  // uniform
    const longlong2* e64 = reinterpret_cast<const longlong2*>(edges);
    const int2* e32 = reinterpret_cast<const int2*>(edges);

    for (int e = blockIdx.x * blockDim.x + threadIdx.x; e < n_edges;
         e += gridDim.x * blockDim.x) {
        long long i, j;
        if (is64) {
            longlong2 ij = e64[e];
            i = ij.x; j = ij.y;
        } else {
            int2 ij = e32[e];
            i = ij.x; j = ij.y;
        }
        // Safety clamp: a bad contract assumption becomes rel_err, not a crash.
        if ((unsigned long long)i >= (unsigned long long)n_nodes ||
            (unsigned long long)j >= (unsigned long long)n_nodes)
            continue;

        float pi = __ldg(&probas[i]);
        float pj = __ldg(&probas[j]);

        bool ms = (pi >= THR_HI) && (pj >= THR_HI);
        bool md = ((pi >= THR_HI) && (pj < THR_LO)) ||
                  ((pj >= THR_HI) && (pi < THR_LO));

        if (ms | md) {
            const float4* fi = reinterpret_cast<const float4*>(feats + i * 64);
            const float4* fj = reinterpret_cast<const float4*>(feats + j * 64);
            float acc = 0.f;
#pragma unroll
            for (int k = 0; k < 16; k++) {
                float4 a = __ldg(&fi[k]);
                float4 b = __ldg(&fj[k]);
                float dx = a.x - b.x, dy = a.y - b.y;
                float dz = a.z - b.z, dw = a.w - b.w;
                acc = fmaf(dx, dx, acc);
                acc = fmaf(dy, dy, acc);
                acc = fmaf(dz, dz, acc);
                acc = fmaf(dw, dw, acc);
            }
            float d = sqrtf(acc);
            if (ms) {
                // bce_sim = -max(log(exp(-d)), -100) = min(d, 100)
                n_sim += 1.f;
                s_sim += fminf(d, 100.f);
            } else {
                // bce_disim = -max(log1p(-exp(-d)), -100)
                float p = expf(-d);
                float l = log1pf(-p);
                n_dis += 1.f;
                s_dis += -fmaxf(l, -100.f);
            }
        }
    }

    // Warp reduce
#pragma unroll
    for (int off = 16; off > 0; off >>= 1) {
        n_sim += __shfl_down_sync(0xFFFFFFFFu, n_sim, off);
        n_dis += __shfl_down_sync(0xFFFFFFFFu, n_dis, off);
        s_sim += __shfl_down_sync(0xFFFFFFFFu, s_sim, off);
        s_dis += __shfl_down_sync(0xFFFFFFFFu, s_dis, off);
    }

    __shared__ float sh[4][8];
    int w = threadIdx.x >> 5, l = threadIdx.x & 31;
    if (l == 0) {
        sh[0][w] = n_sim;
        sh[1][w] = n_dis;
        sh[2][w] = s_sim;
        sh[3][w] = s_dis;
    }
    __syncthreads();

    if (w == 0 && l < 8) {
        float a0 = sh[0][l], a1 = sh[1][l], a2 = sh[2][l], a3 = sh[3][l];
#pragma unroll
        for (int off = 4; off > 0; off >>= 1) {
            a0 += __shfl_down_sync(0xFFu, a0, off);
            a1 += __shfl_down_sync(0xFFu, a1, off);
            a2 += __shfl_down_sync(0xFFu, a2, off);
            a3 += __shfl_down_sync(0xFFu, a3, off);
        }
        if (l == 0) {
            atomicAdd(&g_acc[0], (double)a0);
            atomicAdd(&g_acc[1], (double)a1);
            atomicAdd(&g_acc[2], (double)a2);
            atomicAdd(&g_acc[3], (double)a3);
        }
    }
}

__global__ void lp_finalize_kernel(float* out) {
    double ns = g_acc[0], nd = g_acc[1], ss = g_acc[2], ds = g_acc[3];
    double total = ns + nd;
    double pos_w = nd / total;
    double neg_w = ns / total;
    double loss = (ss * pos_w + ds * neg_w) / total;
    out[0] = (float)loss;
}

extern "C" void kernel_launch(void* const* d_in, const int* in_sizes, int n_in,
                              void* d_out, int out_size) {
    // Identify inputs by element count (robust to metadata ordering):
    //   probas: n_nodes elements (smallest)
    //   feats : n_nodes * 64 elements
    //   edges : n_edges * 2 elements (the remaining one)
    int idx_e = 0, idx_p = 1, idx_f = 2;
    if (n_in == 3) {
        int smallest = 0;
        for (int k = 1; k < 3; k++)
            if (in_sizes[k] < in_sizes[smallest]) smallest = k;
        int pf = -1, ee = -1;
        for (int k = 0; k < 3; k++) {
            if (k == smallest) continue;
            if (in_sizes[k] == in_sizes[smallest] * 64) pf = k;
            else ee = k;
        }
        if (pf >= 0 && ee >= 0) { idx_p = smallest; idx_f = pf; idx_e = ee; }
    }

    const void* edges = d_in[idx_e];
    const float* probas = (const float*)d_in[idx_p];
    const float* feats = (const float*)d_in[idx_f];
    float* out = (float*)d_out;

    int n_edges = in_sizes[idx_e] / 2;
    int n_nodes = in_sizes[idx_p];

    lp_init_kernel<<<1, 32>>>((const int*)edges, in_sizes[idx_e]);
    lp_edge_kernel<<<2048, 256>>>(edges, probas, feats, n_edges, n_nodes);
    lp_finalize_kernel<<<1, 1>>>(out);
}